// round 6
// baseline (speedup 1.0000x reference)
#include <cuda_runtime.h>
#include <math.h>

// Problem constants
#define Bsz 64
#define Tsz 512
#define Dsz 512
#define Hsz 1024

// ===================== Phase 1: xin = x @ W_in^T + b_in + bias =====================
// M = B*T = 32768, K = D = 512, N = H = 1024.  Written directly into d_out.
#define BM 64
#define BN 64
#define BK 32

__global__ __launch_bounds__(256) void gemm_in_kernel(
    const float* __restrict__ x, const float* __restrict__ Win,
    const float* __restrict__ bin, const float* __restrict__ bias,
    float* __restrict__ out)
{
    __shared__ float As[BK][BM];   // x^T tile
    __shared__ float Bs[BK][BN];   // W_in^T tile

    const int m0 = blockIdx.y * BM;
    const int n0 = blockIdx.x * BN;
    const int tid = threadIdx.x;          // 256 threads
    const int tx = tid & 15;               // 0..15  (N microtile)
    const int ty = tid >> 4;               // 0..15  (M microtile)

    float acc[4][4] = {};

    for (int k0 = 0; k0 < Dsz; k0 += BK) {
        // Load 64x32 x-tile and 64x32 W-tile (transposed into smem).
        #pragma unroll
        for (int i = 0; i < 2; i++) {
            int li = tid + i * 256;        // 0..511 float4 slots
            int r  = li >> 3;              // row 0..63
            int c4 = (li & 7) * 4;         // k offset 0,4,..,28
            float4 v = *(const float4*)&x[(m0 + r) * Dsz + k0 + c4];
            As[c4 + 0][r] = v.x; As[c4 + 1][r] = v.y;
            As[c4 + 2][r] = v.z; As[c4 + 3][r] = v.w;
            float4 u = *(const float4*)&Win[(n0 + r) * Dsz + k0 + c4];
            Bs[c4 + 0][r] = u.x; Bs[c4 + 1][r] = u.y;
            Bs[c4 + 2][r] = u.z; Bs[c4 + 3][r] = u.w;
        }
        __syncthreads();

        #pragma unroll
        for (int kk = 0; kk < BK; kk++) {
            float4 av = *(const float4*)&As[kk][ty * 4];
            float4 bv = *(const float4*)&Bs[kk][tx * 4];
            float a[4] = {av.x, av.y, av.z, av.w};
            float b[4] = {bv.x, bv.y, bv.z, bv.w};
            #pragma unroll
            for (int i2 = 0; i2 < 4; i2++)
                #pragma unroll
                for (int j = 0; j < 4; j++)
                    acc[i2][j] = fmaf(a[i2], b[j], acc[i2][j]);
        }
        __syncthreads();
    }

    // Epilogue: add both biases, store (coalesced float4).
    const int n = n0 + tx * 4;
    float bb0 = bin[n + 0] + bias[n + 0];
    float bb1 = bin[n + 1] + bias[n + 1];
    float bb2 = bin[n + 2] + bias[n + 2];
    float bb3 = bin[n + 3] + bias[n + 3];
    #pragma unroll
    for (int i2 = 0; i2 < 4; i2++) {
        int m = m0 + ty * 4 + i2;
        float4 o;
        o.x = acc[i2][0] + bb0;
        o.y = acc[i2][1] + bb1;
        o.z = acc[i2][2] + bb2;
        o.w = acc[i2][3] + bb3;
        *(float4*)&out[m * Hsz + n] = o;
    }
}

// ===================== Phase 2: persistent recurrent scan =====================
// out initially holds xin[B,T,H]; each step t overwrites out[:,t,:] with h_t.
// h_{t-1} is read from out[:,t-1,:].  Grid-wide software barrier per step.
#define G   128      // persistent CTAs (all co-resident: 148 SMs, 48KB smem/CTA)
#define NC  8        // H-columns per CTA

__device__ unsigned g_count = 0;
__device__ volatile unsigned g_sense = 0;

__global__ __launch_bounds__(256) void rnn_scan_kernel(
    const float* __restrict__ Whh, float* __restrict__ out)
{
    __shared__ float Ws[Hsz * NC];        // Ws[k*8 + jj] = Whh[(j0+jj)*H + k]  (32 KB)
    __shared__ float red[NC * 8 * 64];    // [jj][warp][b] partials            (16 KB)

    const int tid   = threadIdx.x;        // 256
    const int w     = tid >> 5;           // warp 0..7 -> k-slice
    const int lane  = tid & 31;
    const int tb    = lane >> 1;          // 0..15 -> 4 batch rows each
    const int tj    = lane & 1;           // 0..1  -> 4 j-columns each
    const int bbase = tb * 4;
    const int kw    = w * 128;
    const int j0    = blockIdx.x * NC;

    // Preload this CTA's W_hh slice once; reused for all 512 steps.
    for (int idx = tid; idx < Hsz * NC; idx += 256) {
        int jj = idx >> 10;               // 0..7
        int k  = idx & 1023;
        Ws[k * NC + jj] = Whh[(j0 + jj) * Hsz + k];
    }
    __syncthreads();

    const int fb = tid >> 2;              // finalize: batch 0..63
    const int fj = tid & 3;               // finalize: jj 0..3 (and +4)

    unsigned sense = 0;

    for (int t = 0; t < Tsz; t++) {
        if (t > 0) {
            float acc[4][4] = {};
            const float* r0 = out + ((bbase + 0) * Tsz + (t - 1)) * Hsz;
            const float* r1 = out + ((bbase + 1) * Tsz + (t - 1)) * Hsz;
            const float* r2 = out + ((bbase + 2) * Tsz + (t - 1)) * Hsz;
            const float* r3 = out + ((bbase + 3) * Tsz + (t - 1)) * Hsz;
            const float* wsBase = Ws + tj * 4;

            #pragma unroll 4
            for (int k = kw; k < kw + 128; k += 4) {
                float4 h0 = *(const float4*)(r0 + k);
                float4 h1 = *(const float4*)(r1 + k);
                float4 h2 = *(const float4*)(r2 + k);
                float4 h3 = *(const float4*)(r3 + k);
                float4 w0 = *(const float4*)(wsBase + (k + 0) * NC);
                float4 w1 = *(const float4*)(wsBase + (k + 1) * NC);
                float4 w2 = *(const float4*)(wsBase + (k + 2) * NC);
                float4 w3 = *(const float4*)(wsBase + (k + 3) * NC);

                #define FMA_ROW(R, hc, wv)                          \
                    acc[R][0] = fmaf(hc, wv.x, acc[R][0]);          \
                    acc[R][1] = fmaf(hc, wv.y, acc[R][1]);          \
                    acc[R][2] = fmaf(hc, wv.z, acc[R][2]);          \
                    acc[R][3] = fmaf(hc, wv.w, acc[R][3]);

                FMA_ROW(0, h0.x, w0) FMA_ROW(0, h0.y, w1) FMA_ROW(0, h0.z, w2) FMA_ROW(0, h0.w, w3)
                FMA_ROW(1, h1.x, w0) FMA_ROW(1, h1.y, w1) FMA_ROW(1, h1.z, w2) FMA_ROW(1, h1.w, w3)
                FMA_ROW(2, h2.x, w0) FMA_ROW(2, h2.y, w1) FMA_ROW(2, h2.z, w2) FMA_ROW(2, h2.w, w3)
                FMA_ROW(3, h3.x, w0) FMA_ROW(3, h3.y, w1) FMA_ROW(3, h3.z, w2) FMA_ROW(3, h3.w, w3)
                #undef FMA_ROW
            }

            // Store per-warp partials: red[jj][warp][b]
            #pragma unroll
            for (int b4 = 0; b4 < 4; b4++)
                #pragma unroll
                for (int j = 0; j < 4; j++)
                    red[(tj * 4 + j) * 512 + w * 64 + bbase + b4] = acc[b4][j];
        }
        __syncthreads();

        // Finalize: reduce 8 warp partials, add xin, tanh, write h_t in place.
        #pragma unroll
        for (int rep = 0; rep < 2; rep++) {
            int jj = fj + rep * 4;
            float s = 0.0f;
            if (t > 0) {
                #pragma unroll
                for (int ww = 0; ww < 8; ww++)
                    s += red[jj * 512 + ww * 64 + fb];
            }
            int idx = (fb * Tsz + t) * Hsz + j0 + jj;
            out[idx] = tanhf(out[idx] + s);
        }
        __threadfence();   // make h_t visible chip-wide before the barrier
        __syncthreads();

        // Sense-reversing grid barrier. 512 even toggles -> state returns to
        // {count=0, sense=0} after the kernel, so graph replays are identical.
        if (tid == 0) {
            unsigned s2 = sense ^ 1u;
            unsigned old = atomicAdd(&g_count, 1u);
            if (old == G - 1) {
                atomicExch(&g_count, 0u);
                __threadfence();
                g_sense = s2;
            } else {
                while (g_sense != s2) { }
            }
            __threadfence();
        }
        sense ^= 1u;
        __syncthreads();
    }
}

// ===================== launch =====================
extern "C" void kernel_launch(void* const* d_in, const int* in_sizes, int n_in,
                              void* d_out, int out_size)
{
    const float* x    = (const float*)d_in[0];   // [B,T,D]
    const float* Win  = (const float*)d_in[1];   // [H,D]
    const float* bin  = (const float*)d_in[2];   // [H]
    const float* Whh  = (const float*)d_in[3];   // [H,H]
    const float* bias = (const float*)d_in[4];   // [H]
    float* out = (float*)d_out;                  // [B,T,H]

    (void)in_sizes; (void)n_in; (void)out_size;

    // Phase 1: xin -> out
    dim3 grid1(Hsz / BN, (Bsz * Tsz) / BM);      // (16, 512)
    gemm_in_kernel<<<grid1, 256>>>(x, Win, bin, bias, out);

    // Phase 2: in-place recurrent scan over T
    rnn_scan_kernel<<<G, 256>>>(Whh, out);
}